// round 15
// baseline (speedup 1.0000x reference)
#include <cuda_runtime.h>
#include <cuda_fp16.h>

// ---------------------------------------------------------------------------
// ModulatedAttLayer  B=256, C=2048, H=W=7 (N=49), INTER=1024
//
// R15: R14 +
//   - k64 pipeline stages for NSPLIT1 GEMMs (g, mask): half the barriers
//   - attention split 2x along o (better k_post occupancy)
// ---------------------------------------------------------------------------

#define BB   256
#define CC   2048
#define NN   49
#define II   1024
#define BN   (BB*NN)      // 12544
#define CN   (CC*NN)      // 100352
#define KSPL 32
#define KPER (CN/KSPL)    // 3136
#define WSZ  (II*CC)      // 2097152

__device__ __align__(16) __half d_xh[(size_t)BN*CC];
__device__ __align__(16) __half d_xl[(size_t)BN*CC];
__device__ __align__(16) __half d_wh[(size_t)3*II*CC];
__device__ __align__(16) __half d_wl[(size_t)3*II*CC];
__device__ __align__(16) __half d_mwh[(size_t)CC*II];
__device__ __align__(16) __half d_maph[(size_t)BN*II];
__device__ float d_proj[(size_t)3*BN*II];
__device__ float d_spart[(size_t)KSPL*BB*NN];
__device__ float d_sp[(size_t)BB*NN];

// ---------------- helpers ----------------------------------------------------
__device__ __forceinline__ void splith(float v, __half& h, __half& l) {
    h = __float2half_rn(v);
    l = __float2half_rn(v - __half2float(h));
}
__device__ __forceinline__ unsigned pack2(__half a, __half b) {
    __half2 t = __halves2half2(a, b);
    return *reinterpret_cast<unsigned*>(&t);
}
__device__ __forceinline__ void mma16(float* d, const unsigned* a, const unsigned* b) {
    asm volatile(
        "mma.sync.aligned.m16n8k16.row.col.f32.f16.f16.f32 "
        "{%0,%1,%2,%3}, {%4,%5,%6,%7}, {%8,%9}, {%0,%1,%2,%3};\n"
        : "+f"(d[0]), "+f"(d[1]), "+f"(d[2]), "+f"(d[3])
        : "r"(a[0]), "r"(a[1]), "r"(a[2]), "r"(a[3]), "r"(b[0]), "r"(b[1]));
}
__device__ __forceinline__ void cpa16s(unsigned s, const __half* g) {
    asm volatile("cp.async.cg.shared.global [%0], [%1], 16;\n" :: "r"(s), "l"(g));
}
__device__ __forceinline__ void cpcommit() { asm volatile("cp.async.commit_group;\n"); }
template<int N>
__device__ __forceinline__ void cpwaitN() {
    asm volatile("cp.async.wait_group %0;\n" :: "n"(N) : "memory");
}
__device__ __forceinline__ void ldsm4(unsigned& r0, unsigned& r1, unsigned& r2,
                                      unsigned& r3, unsigned addr) {
    asm volatile("ldmatrix.sync.aligned.m8n8.x4.shared.b16 {%0,%1,%2,%3}, [%4];"
                 : "=r"(r0), "=r"(r1), "=r"(r2), "=r"(r3) : "r"(addr));
}

// ---------------- GEMM core (k32 stages) — used by NSPLIT3 --------------------
template<int NSPLIT, int STAGES, int K>
__device__ __forceinline__ void gemm_core(
    const __half* __restrict__ A, ptrdiff_t dAl,
    const __half* __restrict__ B, ptrdiff_t dBl,
    unsigned sb, float acc[4][4][4])
{
    constexpr int TILB = 128 * 32 * 2;
    constexpr int STB  = ((NSPLIT == 3) ? 4 : 2) * TILB;
    constexpr int T    = K / 32;
    const int tid = threadIdx.x, lane = tid & 31, wid = tid >> 5;
    const int wm = wid & 1, wn = wid >> 1;

    const int r0 = tid >> 2, ch = tid & 3, r1 = r0 + 64;
    const unsigned d0 = (unsigned)(r0 * 64 + ((ch ^ ((r0 >> 1) & 3)) << 4));
    const unsigned d1 = (unsigned)(r1 * 64 + ((ch ^ ((r1 >> 1) & 3)) << 4));
    const __half* a0p = A + (size_t)r0 * K + ch * 8;
    const __half* a1p = A + (size_t)r1 * K + ch * 8;
    const __half* b0p = B + (size_t)r0 * K + ch * 8;
    const __half* b1p = B + (size_t)r1 * K + ch * 8;

    auto issue = [&](int s, int t) {
        if (t < T) {
            unsigned st = sb + (unsigned)s * STB;
            int ko = t * 32;
            cpa16s(st + d0, a0p + ko);
            cpa16s(st + d1, a1p + ko);
            cpa16s(st + TILB + d0, b0p + ko);
            cpa16s(st + TILB + d1, b1p + ko);
            if (NSPLIT == 3) {
                cpa16s(st + 2 * TILB + d0, a0p + dAl + ko);
                cpa16s(st + 2 * TILB + d1, a1p + dAl + ko);
                cpa16s(st + 3 * TILB + d0, b0p + dBl + ko);
                cpa16s(st + 3 * TILB + d1, b1p + dBl + ko);
            }
        }
        cpcommit();
    };

    const int rr8 = ((lane >> 3) & 1) * 8 + (lane & 7);
    const int qh = lane >> 4;
    int aoff[4], asw[4], boff[2], bsw[2];
    #pragma unroll
    for (int mt = 0; mt < 4; mt++) {
        int mr = wm * 64 + mt * 16 + rr8;
        asw[mt] = (mr >> 1) & 3;
        aoff[mt] = mr * 64;
    }
    #pragma unroll
    for (int p = 0; p < 2; p++) {
        int nr = wn * 32 + p * 16 + rr8;
        bsw[p] = (nr >> 1) & 3;
        boff[p] = nr * 64;
    }

    #pragma unroll
    for (int s = 0; s < STAGES - 1; s++) issue(s, s);

    for (int t = 0; t < T; t++) {
        cpwaitN<STAGES - 2>();
        __syncthreads();
        issue((t + STAGES - 1) % STAGES, t + STAGES - 1);

        unsigned bse = sb + (unsigned)(t % STAGES) * STB;
        unsigned tA  = bse, tB = bse + TILB;
        unsigned tAl = bse + 2 * TILB, tBl = bse + 3 * TILB;

        #pragma unroll
        for (int ks = 0; ks < 2; ks++) {
            int kc = ks * 2 + qh;
            unsigned bh[4][2], bl[4][2];
            #pragma unroll
            for (int p = 0; p < 2; p++) {
                unsigned off = (unsigned)(boff[p] + ((kc ^ bsw[p]) << 4));
                unsigned q0, q1, q2, q3;
                ldsm4(q0, q1, q2, q3, tB + off);
                bh[2 * p][0] = q0; bh[2 * p + 1][0] = q1;
                bh[2 * p][1] = q2; bh[2 * p + 1][1] = q3;
                if (NSPLIT == 3) {
                    ldsm4(q0, q1, q2, q3, tBl + off);
                    bl[2 * p][0] = q0; bl[2 * p + 1][0] = q1;
                    bl[2 * p][1] = q2; bl[2 * p + 1][1] = q3;
                }
            }
            #pragma unroll
            for (int mt = 0; mt < 4; mt++) {
                unsigned off = (unsigned)(aoff[mt] + ((kc ^ asw[mt]) << 4));
                unsigned ah[4], al[4];
                ldsm4(ah[0], ah[1], ah[2], ah[3], tA + off);
                if (NSPLIT == 3)
                    ldsm4(al[0], al[1], al[2], al[3], tAl + off);
                #pragma unroll
                for (int nt = 0; nt < 4; nt++) {
                    if (NSPLIT == 3) {
                        mma16(acc[mt][nt], al, bh[nt]);
                        mma16(acc[mt][nt], ah, bl[nt]);
                    }
                    mma16(acc[mt][nt], ah, bh[nt]);
                }
            }
        }
    }
}

// ---------------- GEMM core (k64 stages) — NSPLIT1 only -----------------------
// stage = A 128x128B (16KB) + B 128x128B (16KB); rows 128B wide, 8 chunks,
// swizzle chunk' = c ^ (r&7). 3 stages = 96KB, 2 CTAs/SM. Half the barriers.
template<int K>
__device__ __forceinline__ void gemm_core64(
    const __half* __restrict__ A,
    const __half* __restrict__ B,
    unsigned sb, float acc[4][4][4])
{
    constexpr int STAGES = 3;
    constexpr unsigned TILB = 128 * 128;   // 16KB
    constexpr unsigned STB  = 2 * TILB;    // 32KB
    constexpr int T = K / 64;
    const int tid = threadIdx.x, lane = tid & 31, wid = tid >> 5;
    const int wm = wid & 1, wn = wid >> 1;

    // cp.async: A 1024 chunks -> 4/thread, B 1024 -> 4/thread
    auto issue = [&](int s, int t) {
        if (t < T) {
            unsigned st = sb + (unsigned)s * STB;
            int k0 = t * 64;
            #pragma unroll
            for (int i = 0; i < 4; i++) {
                int u = tid + i * 256;
                int r = u >> 3, c = u & 7;
                unsigned dst = (unsigned)(r * 128 + ((c ^ (r & 7)) << 4));
                cpa16s(st + dst, A + (size_t)r * K + k0 + c * 8);
                cpa16s(st + TILB + dst, B + (size_t)r * K + k0 + c * 8);
            }
        }
        cpcommit();
    };

    const int rr8 = ((lane >> 3) & 1) * 8 + (lane & 7);
    const int qh = lane >> 4;
    int aoff[4], asw[4], boff[2], bsw[2];
    #pragma unroll
    for (int mt = 0; mt < 4; mt++) {
        int mr = wm * 64 + mt * 16 + rr8;
        asw[mt] = mr & 7;
        aoff[mt] = mr * 128;
    }
    #pragma unroll
    for (int p = 0; p < 2; p++) {
        int nr = wn * 32 + p * 16 + rr8;
        bsw[p] = nr & 7;
        boff[p] = nr * 128;
    }

    #pragma unroll
    for (int s = 0; s < STAGES - 1; s++) issue(s, s);

    for (int t = 0; t < T; t++) {
        cpwaitN<STAGES - 2>();
        __syncthreads();
        issue((t + STAGES - 1) % STAGES, t + STAGES - 1);

        unsigned bse = sb + (unsigned)(t % STAGES) * STB;
        unsigned tA = bse, tB = bse + TILB;

        #pragma unroll
        for (int ks = 0; ks < 4; ks++) {
            int kc = ks * 2 + qh;      // 0..7
            unsigned bh[4][2];
            #pragma unroll
            for (int p = 0; p < 2; p++) {
                unsigned off = (unsigned)(boff[p] + ((kc ^ bsw[p]) << 4));
                unsigned q0, q1, q2, q3;
                ldsm4(q0, q1, q2, q3, tB + off);
                bh[2 * p][0] = q0; bh[2 * p + 1][0] = q1;
                bh[2 * p][1] = q2; bh[2 * p + 1][1] = q3;
            }
            #pragma unroll
            for (int mt = 0; mt < 4; mt++) {
                unsigned off = (unsigned)(aoff[mt] + ((kc ^ asw[mt]) << 4));
                unsigned ah[4];
                ldsm4(ah[0], ah[1], ah[2], ah[3], tA + off);
                #pragma unroll
                for (int nt = 0; nt < 4; nt++)
                    mma16(acc[mt][nt], ah, bh[nt]);
            }
        }
    }
}

// stage acc tile into smem [128][132]
__device__ __forceinline__ void stage_acc(float acc[4][4][4], float* stage) {
    int lane = threadIdx.x & 31, wid = threadIdx.x >> 5;
    int wm = wid & 1, wn = wid >> 1;
    #pragma unroll
    for (int mt = 0; mt < 4; mt++) {
        #pragma unroll
        for (int nt = 0; nt < 4; nt++) {
            #pragma unroll
            for (int h = 0; h < 2; h++) {
                int ml = wm * 64 + mt * 16 + (lane >> 2) + h * 8;
                #pragma unroll
                for (int j = 0; j < 2; j++) {
                    int nl = wn * 32 + nt * 8 + (lane & 3) * 2 + j;
                    stage[ml * 132 + nl] = acc[mt][nt][h * 2 + j];
                }
            }
        }
    }
}

// ---------------- K_prep ------------------------------------------------------
__global__ void __launch_bounds__(256) k_prep(const float* __restrict__ x,
                                              const float* __restrict__ th_w,
                                              const float* __restrict__ ph_w,
                                              const float* __restrict__ g_w,
                                              const float* __restrict__ W_w) {
    __shared__ float s[64][50];
    int bx = blockIdx.x;
    if (bx < 8192) {
        int b = bx >> 5, c0 = (bx & 31) * 64;
        const float* xb = x + (size_t)b * CN;
        for (int e = threadIdx.x; e < 64 * NN; e += 256) {
            int cl = e / NN, n = e - cl * NN;
            s[cl][n] = xb[(c0 + cl) * NN + n];
        }
        __syncthreads();
        for (int e = threadIdx.x; e < 16 * NN; e += 256) {
            int n = e >> 4, clg = (e & 15) * 4;
            __half h[4], l[4];
            #pragma unroll
            for (int k = 0; k < 4; k++) splith(s[clg + k][n], h[k], l[k]);
            size_t o = ((size_t)b * NN + n) * CC + c0 + clg;
            *reinterpret_cast<uint2*>(d_xh + o) =
                make_uint2(pack2(h[0], h[1]), pack2(h[2], h[3]));
            *reinterpret_cast<uint2*>(d_xl + o) =
                make_uint2(pack2(l[0], l[1]), pack2(l[2], l[3]));
        }
    } else {
        int role = (bx - 8192) >> 9;
        size_t base = (size_t)((bx - 8192) & 511) * 4096 + threadIdx.x * 4;
        const float* src = (role == 0) ? th_w : (role == 1) ? ph_w
                         : (role == 2) ? g_w : W_w;
        float4 v[4];
        #pragma unroll
        for (int i = 0; i < 4; i++)
            v[i] = *reinterpret_cast<const float4*>(src + base + i * 1024);
        #pragma unroll
        for (int i = 0; i < 4; i++) {
            size_t idx = base + i * 1024;
            if (role < 2) {
                __half h[4], l[4];
                splith(v[i].x, h[0], l[0]); splith(v[i].y, h[1], l[1]);
                splith(v[i].z, h[2], l[2]); splith(v[i].w, h[3], l[3]);
                size_t off = (size_t)role * WSZ + idx;
                *reinterpret_cast<uint2*>(d_wh + off) =
                    make_uint2(pack2(h[0], h[1]), pack2(h[2], h[3]));
                *reinterpret_cast<uint2*>(d_wl + off) =
                    make_uint2(pack2(l[0], l[1]), pack2(l[2], l[3]));
            } else {
                uint2 pk = make_uint2(
                    pack2(__float2half_rn(v[i].x), __float2half_rn(v[i].y)),
                    pack2(__float2half_rn(v[i].z), __float2half_rn(v[i].w)));
                if (role == 2)
                    *reinterpret_cast<uint2*>(d_wh + 2 * (size_t)WSZ + idx) = pk;
                else
                    *reinterpret_cast<uint2*>(d_mwh + idx) = pk;
            }
        }
    }
}

// ---------------- K_mega: spart first || theta/phi (k32x3) || g (k64) ---------
__global__ void __launch_bounds__(256, 2) k_mega(const float* __restrict__ x,
                                                 const float* __restrict__ fcw,
                                                 const float* __restrict__ th_b,
                                                 const float* __restrict__ ph_b,
                                                 const float* __restrict__ g_b) {
    extern __shared__ __align__(16) __half sdyn[];
    unsigned sb = (unsigned)__cvta_generic_to_shared(sdyn);
    int bid = blockIdx.x;
    int tid = threadIdx.x;

    if (bid >= 256) {
        int gb = bid - 256;
        int role = gb / 784;           // 0 theta, 1 phi, 2 g
        int lb = gb - role * 784;
        int n0 = (lb & 7) * 128, m0 = (lb >> 3) * 128;
        float acc[4][4][4] = {};
        const float* bias;
        if (role < 2) {
            const ptrdiff_t DXL = d_xl - d_xh;
            const ptrdiff_t DWL = d_wl - d_wh;
            const __half* wh = d_wh + (size_t)role * WSZ + (size_t)n0 * CC;
            gemm_core<3, 3, CC>(d_xh + (size_t)m0 * CC, DXL, wh, DWL, sb, acc);
            bias = (role == 0) ? th_b : ph_b;
        } else {
            const __half* wh = d_wh + 2 * (size_t)WSZ + (size_t)n0 * CC;
            gemm_core64<CC>(d_xh + (size_t)m0 * CC, wh, sb, acc);
            bias = g_b;
        }
        float* out = d_proj + (size_t)role * BN * II;
        float* stage = (float*)sdyn;
        __syncthreads();
        stage_acc(acc, stage);
        __syncthreads();
        for (int e = tid; e < 128 * 128; e += 256) {
            int ml = e >> 7, ql = e & 127;
            out[(size_t)(m0 + ml) * II + n0 + ql] = stage[ml * 132 + ql] + bias[n0 + ql];
        }
    } else {
        int sid = bid;
        int b0 = (sid & 7) * 32;
        int ks = sid >> 3;
        float* fc_s = (float*)sdyn;
        float* x_s  = fc_s + 49 * 65;
        int bg = tid >> 5, jg = tid & 31;
        float acc[4][2] = {};
        for (int kc = 0; kc < KPER / 64; kc++) {
            int kb = ks * KPER + kc * 64;
            for (int e = tid; e < 49 * 64; e += 256) {
                int j = e >> 6, kk = e & 63;
                fc_s[j * 65 + kk] = fcw[(size_t)j * CN + kb + kk];
            }
            for (int e = tid; e < 32 * 64; e += 256) {
                int bl = e >> 6, kk = e & 63;
                x_s[bl * 65 + kk] = x[(size_t)(b0 + bl) * CN + kb + kk];
            }
            __syncthreads();
            #pragma unroll 4
            for (int kk = 0; kk < 64; kk++) {
                float f0 = fc_s[jg * 65 + kk];
                float f1 = (jg < 17) ? fc_s[(jg + 32) * 65 + kk] : 0.f;
                #pragma unroll
                for (int i = 0; i < 4; i++) {
                    float xv = x_s[(bg * 4 + i) * 65 + kk];
                    acc[i][0] += xv * f0; acc[i][1] += xv * f1;
                }
            }
            __syncthreads();
        }
        #pragma unroll
        for (int i = 0; i < 4; i++) {
            int b = b0 + bg * 4 + i;
            d_spart[((size_t)ks * BB + b) * NN + jg] = acc[i][0];
            if (jg + 32 < NN)
                d_spart[((size_t)ks * BB + b) * NN + jg + 32] = acc[i][1];
        }
    }
}

// ---------------- K_post: attention (2 halves per batch) || sred ---------------
__global__ void __launch_bounds__(256) k_post(const float* __restrict__ fcb) {
    __shared__ float th_s[4][49][17];
    __shared__ float ph_s[4][49][17];
    __shared__ float sc[49][52];

    if (blockIdx.x >= 2 * BB) {   // --- sred ---
        int b = blockIdx.x - 2 * BB, j = threadIdx.x;
        if (j < NN) {
            float s = fcb[j];
            for (int ks = 0; ks < KSPL; ks++)
                s += d_spart[((size_t)ks * BB + b) * NN + j];
            d_sp[b * NN + j] = s;
        }
        return;
    }

    const float* tx = d_proj;
    const float* px = d_proj + (size_t)BN * II;
    const float* gx = d_proj + (size_t)2 * BN * II;

    int b = blockIdx.x >> 1;
    int half = blockIdx.x & 1;
    int tid = threadIdx.x;
    int g = tid >> 6, t = tid & 63;
    int ng = t >> 3, mg = t & 7;
    bool act = (ng < 7) && (mg < 7);

    float acc[7][7] = {};
    for (int kt = 0; kt < 16; kt++) {
        int kb = g * 256 + kt * 16;
        for (int e = t; e < 49 * 16; e += 64) {
            int r = e >> 4, kk = e & 15;
            th_s[g][r][kk] = tx[((size_t)b * NN + r) * II + kb + kk];
            ph_s[g][r][kk] = px[((size_t)b * NN + r) * II + kb + kk];
        }
        __syncthreads();
        if (act) {
            #pragma unroll
            for (int kk = 0; kk < 16; kk++) {
                float av[7], bv[7];
                #pragma unroll
                for (int i = 0; i < 7; i++) av[i] = th_s[g][ng * 7 + i][kk];
                #pragma unroll
                for (int j = 0; j < 7; j++) bv[j] = ph_s[g][mg * 7 + j][kk];
                #pragma unroll
                for (int i = 0; i < 7; i++)
                    #pragma unroll
                    for (int j = 0; j < 7; j++)
                        acc[i][j] += av[i] * bv[j];
            }
        }
        __syncthreads();
    }
    for (int gg = 0; gg < 4; gg++) {
        if (g == gg && act) {
            #pragma unroll
            for (int i = 0; i < 7; i++)
                #pragma unroll
                for (int j = 0; j < 7; j++) {
                    if (gg == 0) sc[ng * 7 + i][mg * 7 + j] = acc[i][j];
                    else         sc[ng * 7 + i][mg * 7 + j] += acc[i][j];
                }
        }
        __syncthreads();
    }
    if (tid < 49) {
        float mx = -1e30f;
        for (int m = 0; m < NN; m++) mx = fmaxf(mx, sc[tid][m]);
        float s = 0.f;
        for (int m = 0; m < NN; m++) {
            float e = expf(sc[tid][m] - mx);
            sc[tid][m] = e; s += e;
        }
        float inv = 1.f / s;
        for (int m = 0; m < NN; m++) sc[tid][m] *= inv;
    }
    __syncthreads();
    for (int op = 0; op < 2; op++) {
        int o = half * 512 + op * 256 + tid;
        float a2[49];
        #pragma unroll
        for (int n = 0; n < NN; n++) a2[n] = 0.f;
        for (int m = 0; m < NN; m++) {
            float gv = gx[((size_t)b * NN + m) * II + o];
            #pragma unroll
            for (int n = 0; n < NN; n++) a2[n] += sc[n][m] * gv;
        }
        for (int n = 0; n < NN; n++)
            d_maph[((size_t)b * NN + n) * II + o] = __float2half_rn(a2[n]);
    }
}

// ---------------- K_mask: mask GEMM (k64 core) + staged epilogue ---------------
__global__ void __launch_bounds__(256, 2) k_mask_mma(const float* __restrict__ x,
                                                     float* __restrict__ out) {
    extern __shared__ __align__(16) __half sdyn[];
    unsigned sb = (unsigned)__cvta_generic_to_shared(sdyn);
    int n0 = blockIdx.x * 128;   // q tile
    int m0 = blockIdx.y * 128;   // c tile
    int tid = threadIdx.x;
    float acc[4][4][4] = {};
    gemm_core64<II>(d_mwh + (size_t)m0 * II, d_maph + (size_t)n0 * II, sb, acc);

    float* stage = (float*)sdyn;
    __syncthreads();
    stage_acc(acc, stage);
    __syncthreads();
    for (int e = tid; e < 128 * 128; e += 256) {
        int cl = e >> 7, ql = e & 127;
        int q = n0 + ql;
        int b = q / 49, n = q - b * 49;
        size_t idx = ((size_t)b * CC + m0 + cl) * NN + n;
        out[idx] = x[idx] + d_sp[q] * stage[cl * 132 + ql];
    }
}

// ---------------------------------------------------------------------------
extern "C" void kernel_launch(void* const* d_in, const int* in_sizes, int n_in,
                              void* d_out, int out_size) {
    const float* x    = (const float*)d_in[0];
    const float* g_w  = (const float*)d_in[1];
    const float* g_b  = (const float*)d_in[2];
    const float* th_w = (const float*)d_in[3];
    const float* th_b = (const float*)d_in[4];
    const float* ph_w = (const float*)d_in[5];
    const float* ph_b = (const float*)d_in[6];
    const float* W_w  = (const float*)d_in[7];
    const float* fc_w = (const float*)d_in[8];
    const float* fc_b = (const float*)d_in[9];
    float* out = (float*)d_out;
    (void)in_sizes; (void)n_in; (void)out_size;

    const int SMEGA = 96 * 1024;   // k32x3 NSPLIT3 (96KB) == k64x3 NSPLIT1 (96KB)
    const int SMASK = 96 * 1024;   // k64x3 pipeline; stage epilogue 67.6KB fits
    cudaFuncSetAttribute(k_mega,     cudaFuncAttributeMaxDynamicSharedMemorySize, SMEGA);
    cudaFuncSetAttribute(k_mask_mma, cudaFuncAttributeMaxDynamicSharedMemorySize, SMASK);

    k_prep<<<8192 + 4 * 512, 256>>>(x, th_w, ph_w, g_w, W_w);
    k_mega<<<2608, 256, SMEGA>>>(x, fc_w, th_b, ph_b, g_b);
    k_post<<<3 * BB, 256>>>(fc_b);
    k_mask_mma<<<dim3(BN / 128, CC / 128), 256, SMASK>>>(x, out);
}

// round 16
// speedup vs baseline: 1.0072x; 1.0072x over previous
#include <cuda_runtime.h>
#include <cuda_fp16.h>

// ---------------------------------------------------------------------------
// ModulatedAttLayer  B=256, C=2048, H=W=7 (N=49), INTER=1024
//
// R16: R14 base (best verified) + only the profile-validated k64 mask core,
//      + sred-first ordering inside k_post.
//   theta/phi : fp16x3 (k32 x 3 stages); g : fp16 (k32 x 4); mask : fp16 (k64 x 3)
// ---------------------------------------------------------------------------

#define BB   256
#define CC   2048
#define NN   49
#define II   1024
#define BN   (BB*NN)      // 12544
#define CN   (CC*NN)      // 100352
#define KSPL 32
#define KPER (CN/KSPL)    // 3136
#define WSZ  (II*CC)      // 2097152

__device__ __align__(16) __half d_xh[(size_t)BN*CC];
__device__ __align__(16) __half d_xl[(size_t)BN*CC];
__device__ __align__(16) __half d_wh[(size_t)3*II*CC];
__device__ __align__(16) __half d_wl[(size_t)3*II*CC];
__device__ __align__(16) __half d_mwh[(size_t)CC*II];
__device__ __align__(16) __half d_maph[(size_t)BN*II];
__device__ float d_proj[(size_t)3*BN*II];
__device__ float d_spart[(size_t)KSPL*BB*NN];
__device__ float d_sp[(size_t)BB*NN];

// ---------------- helpers ----------------------------------------------------
__device__ __forceinline__ void splith(float v, __half& h, __half& l) {
    h = __float2half_rn(v);
    l = __float2half_rn(v - __half2float(h));
}
__device__ __forceinline__ unsigned pack2(__half a, __half b) {
    __half2 t = __halves2half2(a, b);
    return *reinterpret_cast<unsigned*>(&t);
}
__device__ __forceinline__ void mma16(float* d, const unsigned* a, const unsigned* b) {
    asm volatile(
        "mma.sync.aligned.m16n8k16.row.col.f32.f16.f16.f32 "
        "{%0,%1,%2,%3}, {%4,%5,%6,%7}, {%8,%9}, {%0,%1,%2,%3};\n"
        : "+f"(d[0]), "+f"(d[1]), "+f"(d[2]), "+f"(d[3])
        : "r"(a[0]), "r"(a[1]), "r"(a[2]), "r"(a[3]), "r"(b[0]), "r"(b[1]));
}
__device__ __forceinline__ void cpa16s(unsigned s, const __half* g) {
    asm volatile("cp.async.cg.shared.global [%0], [%1], 16;\n" :: "r"(s), "l"(g));
}
__device__ __forceinline__ void cpcommit() { asm volatile("cp.async.commit_group;\n"); }
template<int N>
__device__ __forceinline__ void cpwaitN() {
    asm volatile("cp.async.wait_group %0;\n" :: "n"(N) : "memory");
}
__device__ __forceinline__ void ldsm4(unsigned& r0, unsigned& r1, unsigned& r2,
                                      unsigned& r3, unsigned addr) {
    asm volatile("ldmatrix.sync.aligned.m8n8.x4.shared.b16 {%0,%1,%2,%3}, [%4];"
                 : "=r"(r0), "=r"(r1), "=r"(r2), "=r"(r3) : "r"(addr));
}

// ---------------- GEMM core (k32 stages) ---------------------------------------
template<int NSPLIT, int STAGES, int K>
__device__ __forceinline__ void gemm_core(
    const __half* __restrict__ A, ptrdiff_t dAl,
    const __half* __restrict__ B, ptrdiff_t dBl,
    unsigned sb, float acc[4][4][4])
{
    constexpr int TILB = 128 * 32 * 2;
    constexpr int STB  = ((NSPLIT == 3) ? 4 : 2) * TILB;
    constexpr int T    = K / 32;
    const int tid = threadIdx.x, lane = tid & 31, wid = tid >> 5;
    const int wm = wid & 1, wn = wid >> 1;

    const int r0 = tid >> 2, ch = tid & 3, r1 = r0 + 64;
    const unsigned d0 = (unsigned)(r0 * 64 + ((ch ^ ((r0 >> 1) & 3)) << 4));
    const unsigned d1 = (unsigned)(r1 * 64 + ((ch ^ ((r1 >> 1) & 3)) << 4));
    const __half* a0p = A + (size_t)r0 * K + ch * 8;
    const __half* a1p = A + (size_t)r1 * K + ch * 8;
    const __half* b0p = B + (size_t)r0 * K + ch * 8;
    const __half* b1p = B + (size_t)r1 * K + ch * 8;

    auto issue = [&](int s, int t) {
        if (t < T) {
            unsigned st = sb + (unsigned)s * STB;
            int ko = t * 32;
            cpa16s(st + d0, a0p + ko);
            cpa16s(st + d1, a1p + ko);
            cpa16s(st + TILB + d0, b0p + ko);
            cpa16s(st + TILB + d1, b1p + ko);
            if (NSPLIT == 3) {
                cpa16s(st + 2 * TILB + d0, a0p + dAl + ko);
                cpa16s(st + 2 * TILB + d1, a1p + dAl + ko);
                cpa16s(st + 3 * TILB + d0, b0p + dBl + ko);
                cpa16s(st + 3 * TILB + d1, b1p + dBl + ko);
            }
        }
        cpcommit();
    };

    const int rr8 = ((lane >> 3) & 1) * 8 + (lane & 7);
    const int qh = lane >> 4;
    int aoff[4], asw[4], boff[2], bsw[2];
    #pragma unroll
    for (int mt = 0; mt < 4; mt++) {
        int mr = wm * 64 + mt * 16 + rr8;
        asw[mt] = (mr >> 1) & 3;
        aoff[mt] = mr * 64;
    }
    #pragma unroll
    for (int p = 0; p < 2; p++) {
        int nr = wn * 32 + p * 16 + rr8;
        bsw[p] = (nr >> 1) & 3;
        boff[p] = nr * 64;
    }

    #pragma unroll
    for (int s = 0; s < STAGES - 1; s++) issue(s, s);

    for (int t = 0; t < T; t++) {
        cpwaitN<STAGES - 2>();
        __syncthreads();
        issue((t + STAGES - 1) % STAGES, t + STAGES - 1);

        unsigned bse = sb + (unsigned)(t % STAGES) * STB;
        unsigned tA  = bse, tB = bse + TILB;
        unsigned tAl = bse + 2 * TILB, tBl = bse + 3 * TILB;

        #pragma unroll
        for (int ks = 0; ks < 2; ks++) {
            int kc = ks * 2 + qh;
            unsigned bh[4][2], bl[4][2];
            #pragma unroll
            for (int p = 0; p < 2; p++) {
                unsigned off = (unsigned)(boff[p] + ((kc ^ bsw[p]) << 4));
                unsigned q0, q1, q2, q3;
                ldsm4(q0, q1, q2, q3, tB + off);
                bh[2 * p][0] = q0; bh[2 * p + 1][0] = q1;
                bh[2 * p][1] = q2; bh[2 * p + 1][1] = q3;
                if (NSPLIT == 3) {
                    ldsm4(q0, q1, q2, q3, tBl + off);
                    bl[2 * p][0] = q0; bl[2 * p + 1][0] = q1;
                    bl[2 * p][1] = q2; bl[2 * p + 1][1] = q3;
                }
            }
            #pragma unroll
            for (int mt = 0; mt < 4; mt++) {
                unsigned off = (unsigned)(aoff[mt] + ((kc ^ asw[mt]) << 4));
                unsigned ah[4], al[4];
                ldsm4(ah[0], ah[1], ah[2], ah[3], tA + off);
                if (NSPLIT == 3)
                    ldsm4(al[0], al[1], al[2], al[3], tAl + off);
                #pragma unroll
                for (int nt = 0; nt < 4; nt++) {
                    if (NSPLIT == 3) {
                        mma16(acc[mt][nt], al, bh[nt]);
                        mma16(acc[mt][nt], ah, bl[nt]);
                    }
                    mma16(acc[mt][nt], ah, bh[nt]);
                }
            }
        }
    }
}

// ---------------- GEMM core (k64 stages) — mask only ---------------------------
template<int K>
__device__ __forceinline__ void gemm_core64(
    const __half* __restrict__ A,
    const __half* __restrict__ B,
    unsigned sb, float acc[4][4][4])
{
    constexpr int STAGES = 3;
    constexpr unsigned TILB = 128 * 128;   // 16KB
    constexpr unsigned STB  = 2 * TILB;    // 32KB
    constexpr int T = K / 64;
    const int tid = threadIdx.x, lane = tid & 31, wid = tid >> 5;
    const int wm = wid & 1, wn = wid >> 1;

    auto issue = [&](int s, int t) {
        if (t < T) {
            unsigned st = sb + (unsigned)s * STB;
            int k0 = t * 64;
            #pragma unroll
            for (int i = 0; i < 4; i++) {
                int u = tid + i * 256;
                int r = u >> 3, c = u & 7;
                unsigned dst = (unsigned)(r * 128 + ((c ^ (r & 7)) << 4));
                cpa16s(st + dst, A + (size_t)r * K + k0 + c * 8);
                cpa16s(st + TILB + dst, B + (size_t)r * K + k0 + c * 8);
            }
        }
        cpcommit();
    };

    const int rr8 = ((lane >> 3) & 1) * 8 + (lane & 7);
    const int qh = lane >> 4;
    int aoff[4], asw[4], boff[2], bsw[2];
    #pragma unroll
    for (int mt = 0; mt < 4; mt++) {
        int mr = wm * 64 + mt * 16 + rr8;
        asw[mt] = mr & 7;
        aoff[mt] = mr * 128;
    }
    #pragma unroll
    for (int p = 0; p < 2; p++) {
        int nr = wn * 32 + p * 16 + rr8;
        bsw[p] = nr & 7;
        boff[p] = nr * 128;
    }

    #pragma unroll
    for (int s = 0; s < STAGES - 1; s++) issue(s, s);

    for (int t = 0; t < T; t++) {
        cpwaitN<STAGES - 2>();
        __syncthreads();
        issue((t + STAGES - 1) % STAGES, t + STAGES - 1);

        unsigned bse = sb + (unsigned)(t % STAGES) * STB;
        unsigned tA = bse, tB = bse + TILB;

        #pragma unroll
        for (int ks = 0; ks < 4; ks++) {
            int kc = ks * 2 + qh;
            unsigned bh[4][2];
            #pragma unroll
            for (int p = 0; p < 2; p++) {
                unsigned off = (unsigned)(boff[p] + ((kc ^ bsw[p]) << 4));
                unsigned q0, q1, q2, q3;
                ldsm4(q0, q1, q2, q3, tB + off);
                bh[2 * p][0] = q0; bh[2 * p + 1][0] = q1;
                bh[2 * p][1] = q2; bh[2 * p + 1][1] = q3;
            }
            #pragma unroll
            for (int mt = 0; mt < 4; mt++) {
                unsigned off = (unsigned)(aoff[mt] + ((kc ^ asw[mt]) << 4));
                unsigned ah[4];
                ldsm4(ah[0], ah[1], ah[2], ah[3], tA + off);
                #pragma unroll
                for (int nt = 0; nt < 4; nt++)
                    mma16(acc[mt][nt], ah, bh[nt]);
            }
        }
    }
}

// stage acc tile into smem [128][132]
__device__ __forceinline__ void stage_acc(float acc[4][4][4], float* stage) {
    int lane = threadIdx.x & 31, wid = threadIdx.x >> 5;
    int wm = wid & 1, wn = wid >> 1;
    #pragma unroll
    for (int mt = 0; mt < 4; mt++) {
        #pragma unroll
        for (int nt = 0; nt < 4; nt++) {
            #pragma unroll
            for (int h = 0; h < 2; h++) {
                int ml = wm * 64 + mt * 16 + (lane >> 2) + h * 8;
                #pragma unroll
                for (int j = 0; j < 2; j++) {
                    int nl = wn * 32 + nt * 8 + (lane & 3) * 2 + j;
                    stage[ml * 132 + nl] = acc[mt][nt][h * 2 + j];
                }
            }
        }
    }
}

// ---------------- K_prep ------------------------------------------------------
__global__ void __launch_bounds__(256) k_prep(const float* __restrict__ x,
                                              const float* __restrict__ th_w,
                                              const float* __restrict__ ph_w,
                                              const float* __restrict__ g_w,
                                              const float* __restrict__ W_w) {
    __shared__ float s[64][50];
    int bx = blockIdx.x;
    if (bx < 8192) {
        int b = bx >> 5, c0 = (bx & 31) * 64;
        const float* xb = x + (size_t)b * CN;
        for (int e = threadIdx.x; e < 64 * NN; e += 256) {
            int cl = e / NN, n = e - cl * NN;
            s[cl][n] = xb[(c0 + cl) * NN + n];
        }
        __syncthreads();
        for (int e = threadIdx.x; e < 16 * NN; e += 256) {
            int n = e >> 4, clg = (e & 15) * 4;
            __half h[4], l[4];
            #pragma unroll
            for (int k = 0; k < 4; k++) splith(s[clg + k][n], h[k], l[k]);
            size_t o = ((size_t)b * NN + n) * CC + c0 + clg;
            *reinterpret_cast<uint2*>(d_xh + o) =
                make_uint2(pack2(h[0], h[1]), pack2(h[2], h[3]));
            *reinterpret_cast<uint2*>(d_xl + o) =
                make_uint2(pack2(l[0], l[1]), pack2(l[2], l[3]));
        }
    } else {
        int role = (bx - 8192) >> 9;
        size_t base = (size_t)((bx - 8192) & 511) * 4096 + threadIdx.x * 4;
        const float* src = (role == 0) ? th_w : (role == 1) ? ph_w
                         : (role == 2) ? g_w : W_w;
        float4 v[4];
        #pragma unroll
        for (int i = 0; i < 4; i++)
            v[i] = *reinterpret_cast<const float4*>(src + base + i * 1024);
        #pragma unroll
        for (int i = 0; i < 4; i++) {
            size_t idx = base + i * 1024;
            if (role < 2) {
                __half h[4], l[4];
                splith(v[i].x, h[0], l[0]); splith(v[i].y, h[1], l[1]);
                splith(v[i].z, h[2], l[2]); splith(v[i].w, h[3], l[3]);
                size_t off = (size_t)role * WSZ + idx;
                *reinterpret_cast<uint2*>(d_wh + off) =
                    make_uint2(pack2(h[0], h[1]), pack2(h[2], h[3]));
                *reinterpret_cast<uint2*>(d_wl + off) =
                    make_uint2(pack2(l[0], l[1]), pack2(l[2], l[3]));
            } else {
                uint2 pk = make_uint2(
                    pack2(__float2half_rn(v[i].x), __float2half_rn(v[i].y)),
                    pack2(__float2half_rn(v[i].z), __float2half_rn(v[i].w)));
                if (role == 2)
                    *reinterpret_cast<uint2*>(d_wh + 2 * (size_t)WSZ + idx) = pk;
                else
                    *reinterpret_cast<uint2*>(d_mwh + idx) = pk;
            }
        }
    }
}

// ---------------- K_mega: spart first || theta/phi (k32x3) || g (k32x4) -------
__global__ void __launch_bounds__(256, 2) k_mega(const float* __restrict__ x,
                                                 const float* __restrict__ fcw,
                                                 const float* __restrict__ th_b,
                                                 const float* __restrict__ ph_b,
                                                 const float* __restrict__ g_b) {
    extern __shared__ __align__(16) __half sdyn[];
    unsigned sb = (unsigned)__cvta_generic_to_shared(sdyn);
    int bid = blockIdx.x;
    int tid = threadIdx.x;

    if (bid >= 256) {
        int gb = bid - 256;
        int role = gb / 784;           // 0 theta, 1 phi, 2 g
        int lb = gb - role * 784;
        int n0 = (lb & 7) * 128, m0 = (lb >> 3) * 128;
        float acc[4][4][4] = {};
        const float* bias;
        if (role < 2) {
            const ptrdiff_t DXL = d_xl - d_xh;
            const ptrdiff_t DWL = d_wl - d_wh;
            const __half* wh = d_wh + (size_t)role * WSZ + (size_t)n0 * CC;
            gemm_core<3, 3, CC>(d_xh + (size_t)m0 * CC, DXL, wh, DWL, sb, acc);
            bias = (role == 0) ? th_b : ph_b;
        } else {
            const __half* wh = d_wh + 2 * (size_t)WSZ + (size_t)n0 * CC;
            gemm_core<1, 4, CC>(d_xh + (size_t)m0 * CC, 0, wh, 0, sb, acc);
            bias = g_b;
        }
        float* out = d_proj + (size_t)role * BN * II;
        float* stage = (float*)sdyn;
        __syncthreads();
        stage_acc(acc, stage);
        __syncthreads();
        for (int e = tid; e < 128 * 128; e += 256) {
            int ml = e >> 7, ql = e & 127;
            out[(size_t)(m0 + ml) * II + n0 + ql] = stage[ml * 132 + ql] + bias[n0 + ql];
        }
    } else {
        int sid = bid;
        int b0 = (sid & 7) * 32;
        int ks = sid >> 3;
        float* fc_s = (float*)sdyn;
        float* x_s  = fc_s + 49 * 65;
        int bg = tid >> 5, jg = tid & 31;
        float acc[4][2] = {};
        for (int kc = 0; kc < KPER / 64; kc++) {
            int kb = ks * KPER + kc * 64;
            for (int e = tid; e < 49 * 64; e += 256) {
                int j = e >> 6, kk = e & 63;
                fc_s[j * 65 + kk] = fcw[(size_t)j * CN + kb + kk];
            }
            for (int e = tid; e < 32 * 64; e += 256) {
                int bl = e >> 6, kk = e & 63;
                x_s[bl * 65 + kk] = x[(size_t)(b0 + bl) * CN + kb + kk];
            }
            __syncthreads();
            #pragma unroll 4
            for (int kk = 0; kk < 64; kk++) {
                float f0 = fc_s[jg * 65 + kk];
                float f1 = (jg < 17) ? fc_s[(jg + 32) * 65 + kk] : 0.f;
                #pragma unroll
                for (int i = 0; i < 4; i++) {
                    float xv = x_s[(bg * 4 + i) * 65 + kk];
                    acc[i][0] += xv * f0; acc[i][1] += xv * f1;
                }
            }
            __syncthreads();
        }
        #pragma unroll
        for (int i = 0; i < 4; i++) {
            int b = b0 + bg * 4 + i;
            d_spart[((size_t)ks * BB + b) * NN + jg] = acc[i][0];
            if (jg + 32 < NN)
                d_spart[((size_t)ks * BB + b) * NN + jg + 32] = acc[i][1];
        }
    }
}

// ---------------- K_post: sred FIRST || attention ------------------------------
__global__ void __launch_bounds__(256) k_post(const float* __restrict__ fcb) {
    __shared__ float th_s[4][49][17];
    __shared__ float ph_s[4][49][17];
    __shared__ float sc[49][52];

    if (blockIdx.x < BB) {   // --- sred (memory-light, wave 1) ---
        int b = blockIdx.x, j = threadIdx.x;
        if (j < NN) {
            float s = fcb[j];
            for (int ks = 0; ks < KSPL; ks++)
                s += d_spart[((size_t)ks * BB + b) * NN + j];
            d_sp[b * NN + j] = s;
        }
        return;
    }

    const float* tx = d_proj;
    const float* px = d_proj + (size_t)BN * II;
    const float* gx = d_proj + (size_t)2 * BN * II;

    int b = blockIdx.x - BB;
    int tid = threadIdx.x;
    int g = tid >> 6, t = tid & 63;
    int ng = t >> 3, mg = t & 7;
    bool act = (ng < 7) && (mg < 7);

    float acc[7][7] = {};
    for (int kt = 0; kt < 16; kt++) {
        int kb = g * 256 + kt * 16;
        for (int e = t; e < 49 * 16; e += 64) {
            int r = e >> 4, kk = e & 15;
            th_s[g][r][kk] = tx[((size_t)b * NN + r) * II + kb + kk];
            ph_s[g][r][kk] = px[((size_t)b * NN + r) * II + kb + kk];
        }
        __syncthreads();
        if (act) {
            #pragma unroll
            for (int kk = 0; kk < 16; kk++) {
                float av[7], bv[7];
                #pragma unroll
                for (int i = 0; i < 7; i++) av[i] = th_s[g][ng * 7 + i][kk];
                #pragma unroll
                for (int j = 0; j < 7; j++) bv[j] = ph_s[g][mg * 7 + j][kk];
                #pragma unroll
                for (int i = 0; i < 7; i++)
                    #pragma unroll
                    for (int j = 0; j < 7; j++)
                        acc[i][j] += av[i] * bv[j];
            }
        }
        __syncthreads();
    }
    for (int gg = 0; gg < 4; gg++) {
        if (g == gg && act) {
            #pragma unroll
            for (int i = 0; i < 7; i++)
                #pragma unroll
                for (int j = 0; j < 7; j++) {
                    if (gg == 0) sc[ng * 7 + i][mg * 7 + j] = acc[i][j];
                    else         sc[ng * 7 + i][mg * 7 + j] += acc[i][j];
                }
        }
        __syncthreads();
    }
    if (tid < 49) {
        float mx = -1e30f;
        for (int m = 0; m < NN; m++) mx = fmaxf(mx, sc[tid][m]);
        float s = 0.f;
        for (int m = 0; m < NN; m++) {
            float e = expf(sc[tid][m] - mx);
            sc[tid][m] = e; s += e;
        }
        float inv = 1.f / s;
        for (int m = 0; m < NN; m++) sc[tid][m] *= inv;
    }
    __syncthreads();
    for (int op = 0; op < 4; op++) {
        int o = op * 256 + tid;
        float a2[49];
        #pragma unroll
        for (int n = 0; n < NN; n++) a2[n] = 0.f;
        for (int m = 0; m < NN; m++) {
            float gv = gx[((size_t)b * NN + m) * II + o];
            #pragma unroll
            for (int n = 0; n < NN; n++) a2[n] += sc[n][m] * gv;
        }
        for (int n = 0; n < NN; n++)
            d_maph[((size_t)b * NN + n) * II + o] = __float2half_rn(a2[n]);
    }
}

// ---------------- K_mask: mask GEMM (k64 core) + staged epilogue ---------------
__global__ void __launch_bounds__(256, 2) k_mask_mma(const float* __restrict__ x,
                                                     float* __restrict__ out) {
    extern __shared__ __align__(16) __half sdyn[];
    unsigned sb = (unsigned)__cvta_generic_to_shared(sdyn);
    int n0 = blockIdx.x * 128;
    int m0 = blockIdx.y * 128;
    int tid = threadIdx.x;
    float acc[4][4][4] = {};
    gemm_core64<II>(d_mwh + (size_t)m0 * II, d_maph + (size_t)n0 * II, sb, acc);

    float* stage = (float*)sdyn;
    __syncthreads();
    stage_acc(acc, stage);
    __syncthreads();
    for (int e = tid; e < 128 * 128; e += 256) {
        int cl = e >> 7, ql = e & 127;
        int q = n0 + ql;
        int b = q / 49, n = q - b * 49;
        size_t idx = ((size_t)b * CC + m0 + cl) * NN + n;
        out[idx] = x[idx] + d_sp[q] * stage[cl * 132 + ql];
    }
}

// ---------------------------------------------------------------------------
extern "C" void kernel_launch(void* const* d_in, const int* in_sizes, int n_in,
                              void* d_out, int out_size) {
    const float* x    = (const float*)d_in[0];
    const float* g_w  = (const float*)d_in[1];
    const float* g_b  = (const float*)d_in[2];
    const float* th_w = (const float*)d_in[3];
    const float* th_b = (const float*)d_in[4];
    const float* ph_w = (const float*)d_in[5];
    const float* ph_b = (const float*)d_in[6];
    const float* W_w  = (const float*)d_in[7];
    const float* fc_w = (const float*)d_in[8];
    const float* fc_b = (const float*)d_in[9];
    float* out = (float*)d_out;
    (void)in_sizes; (void)n_in; (void)out_size;

    const int SMEGA = 96 * 1024;   // k32x3 NSPLIT3 / k32x4 NSPLIT1 / stage 67.6KB
    const int SMASK = 96 * 1024;   // k64x3 pipeline; stage epilogue fits
    cudaFuncSetAttribute(k_mega,     cudaFuncAttributeMaxDynamicSharedMemorySize, SMEGA);
    cudaFuncSetAttribute(k_mask_mma, cudaFuncAttributeMaxDynamicSharedMemorySize, SMASK);

    k_prep<<<8192 + 4 * 512, 256>>>(x, th_w, ph_w, g_w, W_w);
    k_mega<<<2608, 256, SMEGA>>>(x, fc_w, th_b, ph_b, g_b);
    k_post<<<2 * BB, 256>>>(fc_b);
    k_mask_mma<<<dim3(BN / 128, CC / 128), 256, SMASK>>>(x, out);
}

// round 17
// speedup vs baseline: 1.0202x; 1.0128x over previous
#include <cuda_runtime.h>
#include <cuda_fp16.h>

// ---------------------------------------------------------------------------
// ModulatedAttLayer  B=256, C=2048, H=W=7 (N=49), INTER=1024
//
// R17: R14 (best verified, 1625us) + ONLY the profile-validated k64 mask core.
//   theta/phi : fp16x3 (k32 x 3 stages); g : fp16 (k32 x 4); mask : fp16 (k64 x 3)
//   k_mega: spart first; k_post: attention blocks first, sred after (R14 order).
// ---------------------------------------------------------------------------

#define BB   256
#define CC   2048
#define NN   49
#define II   1024
#define BN   (BB*NN)      // 12544
#define CN   (CC*NN)      // 100352
#define KSPL 32
#define KPER (CN/KSPL)    // 3136
#define WSZ  (II*CC)      // 2097152

__device__ __align__(16) __half d_xh[(size_t)BN*CC];
__device__ __align__(16) __half d_xl[(size_t)BN*CC];
__device__ __align__(16) __half d_wh[(size_t)3*II*CC];
__device__ __align__(16) __half d_wl[(size_t)3*II*CC];
__device__ __align__(16) __half d_mwh[(size_t)CC*II];
__device__ __align__(16) __half d_maph[(size_t)BN*II];
__device__ float d_proj[(size_t)3*BN*II];
__device__ float d_spart[(size_t)KSPL*BB*NN];
__device__ float d_sp[(size_t)BB*NN];

// ---------------- helpers ----------------------------------------------------
__device__ __forceinline__ void splith(float v, __half& h, __half& l) {
    h = __float2half_rn(v);
    l = __float2half_rn(v - __half2float(h));
}
__device__ __forceinline__ unsigned pack2(__half a, __half b) {
    __half2 t = __halves2half2(a, b);
    return *reinterpret_cast<unsigned*>(&t);
}
__device__ __forceinline__ void mma16(float* d, const unsigned* a, const unsigned* b) {
    asm volatile(
        "mma.sync.aligned.m16n8k16.row.col.f32.f16.f16.f32 "
        "{%0,%1,%2,%3}, {%4,%5,%6,%7}, {%8,%9}, {%0,%1,%2,%3};\n"
        : "+f"(d[0]), "+f"(d[1]), "+f"(d[2]), "+f"(d[3])
        : "r"(a[0]), "r"(a[1]), "r"(a[2]), "r"(a[3]), "r"(b[0]), "r"(b[1]));
}
__device__ __forceinline__ void cpa16s(unsigned s, const __half* g) {
    asm volatile("cp.async.cg.shared.global [%0], [%1], 16;\n" :: "r"(s), "l"(g));
}
__device__ __forceinline__ void cpcommit() { asm volatile("cp.async.commit_group;\n"); }
template<int N>
__device__ __forceinline__ void cpwaitN() {
    asm volatile("cp.async.wait_group %0;\n" :: "n"(N) : "memory");
}
__device__ __forceinline__ void ldsm4(unsigned& r0, unsigned& r1, unsigned& r2,
                                      unsigned& r3, unsigned addr) {
    asm volatile("ldmatrix.sync.aligned.m8n8.x4.shared.b16 {%0,%1,%2,%3}, [%4];"
                 : "=r"(r0), "=r"(r1), "=r"(r2), "=r"(r3) : "r"(addr));
}

// ---------------- GEMM core (k32 stages) ---------------------------------------
template<int NSPLIT, int STAGES, int K>
__device__ __forceinline__ void gemm_core(
    const __half* __restrict__ A, ptrdiff_t dAl,
    const __half* __restrict__ B, ptrdiff_t dBl,
    unsigned sb, float acc[4][4][4])
{
    constexpr int TILB = 128 * 32 * 2;
    constexpr int STB  = ((NSPLIT == 3) ? 4 : 2) * TILB;
    constexpr int T    = K / 32;
    const int tid = threadIdx.x, lane = tid & 31, wid = tid >> 5;
    const int wm = wid & 1, wn = wid >> 1;

    const int r0 = tid >> 2, ch = tid & 3, r1 = r0 + 64;
    const unsigned d0 = (unsigned)(r0 * 64 + ((ch ^ ((r0 >> 1) & 3)) << 4));
    const unsigned d1 = (unsigned)(r1 * 64 + ((ch ^ ((r1 >> 1) & 3)) << 4));
    const __half* a0p = A + (size_t)r0 * K + ch * 8;
    const __half* a1p = A + (size_t)r1 * K + ch * 8;
    const __half* b0p = B + (size_t)r0 * K + ch * 8;
    const __half* b1p = B + (size_t)r1 * K + ch * 8;

    auto issue = [&](int s, int t) {
        if (t < T) {
            unsigned st = sb + (unsigned)s * STB;
            int ko = t * 32;
            cpa16s(st + d0, a0p + ko);
            cpa16s(st + d1, a1p + ko);
            cpa16s(st + TILB + d0, b0p + ko);
            cpa16s(st + TILB + d1, b1p + ko);
            if (NSPLIT == 3) {
                cpa16s(st + 2 * TILB + d0, a0p + dAl + ko);
                cpa16s(st + 2 * TILB + d1, a1p + dAl + ko);
                cpa16s(st + 3 * TILB + d0, b0p + dBl + ko);
                cpa16s(st + 3 * TILB + d1, b1p + dBl + ko);
            }
        }
        cpcommit();
    };

    const int rr8 = ((lane >> 3) & 1) * 8 + (lane & 7);
    const int qh = lane >> 4;
    int aoff[4], asw[4], boff[2], bsw[2];
    #pragma unroll
    for (int mt = 0; mt < 4; mt++) {
        int mr = wm * 64 + mt * 16 + rr8;
        asw[mt] = (mr >> 1) & 3;
        aoff[mt] = mr * 64;
    }
    #pragma unroll
    for (int p = 0; p < 2; p++) {
        int nr = wn * 32 + p * 16 + rr8;
        bsw[p] = (nr >> 1) & 3;
        boff[p] = nr * 64;
    }

    #pragma unroll
    for (int s = 0; s < STAGES - 1; s++) issue(s, s);

    for (int t = 0; t < T; t++) {
        cpwaitN<STAGES - 2>();
        __syncthreads();
        issue((t + STAGES - 1) % STAGES, t + STAGES - 1);

        unsigned bse = sb + (unsigned)(t % STAGES) * STB;
        unsigned tA  = bse, tB = bse + TILB;
        unsigned tAl = bse + 2 * TILB, tBl = bse + 3 * TILB;

        #pragma unroll
        for (int ks = 0; ks < 2; ks++) {
            int kc = ks * 2 + qh;
            unsigned bh[4][2], bl[4][2];
            #pragma unroll
            for (int p = 0; p < 2; p++) {
                unsigned off = (unsigned)(boff[p] + ((kc ^ bsw[p]) << 4));
                unsigned q0, q1, q2, q3;
                ldsm4(q0, q1, q2, q3, tB + off);
                bh[2 * p][0] = q0; bh[2 * p + 1][0] = q1;
                bh[2 * p][1] = q2; bh[2 * p + 1][1] = q3;
                if (NSPLIT == 3) {
                    ldsm4(q0, q1, q2, q3, tBl + off);
                    bl[2 * p][0] = q0; bl[2 * p + 1][0] = q1;
                    bl[2 * p][1] = q2; bl[2 * p + 1][1] = q3;
                }
            }
            #pragma unroll
            for (int mt = 0; mt < 4; mt++) {
                unsigned off = (unsigned)(aoff[mt] + ((kc ^ asw[mt]) << 4));
                unsigned ah[4], al[4];
                ldsm4(ah[0], ah[1], ah[2], ah[3], tA + off);
                if (NSPLIT == 3)
                    ldsm4(al[0], al[1], al[2], al[3], tAl + off);
                #pragma unroll
                for (int nt = 0; nt < 4; nt++) {
                    if (NSPLIT == 3) {
                        mma16(acc[mt][nt], al, bh[nt]);
                        mma16(acc[mt][nt], ah, bl[nt]);
                    }
                    mma16(acc[mt][nt], ah, bh[nt]);
                }
            }
        }
    }
}

// ---------------- GEMM core (k64 stages) — mask only ---------------------------
template<int K>
__device__ __forceinline__ void gemm_core64(
    const __half* __restrict__ A,
    const __half* __restrict__ B,
    unsigned sb, float acc[4][4][4])
{
    constexpr int STAGES = 3;
    constexpr unsigned TILB = 128 * 128;   // 16KB
    constexpr unsigned STB  = 2 * TILB;    // 32KB
    constexpr int T = K / 64;
    const int tid = threadIdx.x, lane = tid & 31, wid = tid >> 5;
    const int wm = wid & 1, wn = wid >> 1;

    auto issue = [&](int s, int t) {
        if (t < T) {
            unsigned st = sb + (unsigned)s * STB;
            int k0 = t * 64;
            #pragma unroll
            for (int i = 0; i < 4; i++) {
                int u = tid + i * 256;
                int r = u >> 3, c = u & 7;
                unsigned dst = (unsigned)(r * 128 + ((c ^ (r & 7)) << 4));
                cpa16s(st + dst, A + (size_t)r * K + k0 + c * 8);
                cpa16s(st + TILB + dst, B + (size_t)r * K + k0 + c * 8);
            }
        }
        cpcommit();
    };

    const int rr8 = ((lane >> 3) & 1) * 8 + (lane & 7);
    const int qh = lane >> 4;
    int aoff[4], asw[4], boff[2], bsw[2];
    #pragma unroll
    for (int mt = 0; mt < 4; mt++) {
        int mr = wm * 64 + mt * 16 + rr8;
        asw[mt] = mr & 7;
        aoff[mt] = mr * 128;
    }
    #pragma unroll
    for (int p = 0; p < 2; p++) {
        int nr = wn * 32 + p * 16 + rr8;
        bsw[p] = nr & 7;
        boff[p] = nr * 128;
    }

    #pragma unroll
    for (int s = 0; s < STAGES - 1; s++) issue(s, s);

    for (int t = 0; t < T; t++) {
        cpwaitN<STAGES - 2>();
        __syncthreads();
        issue((t + STAGES - 1) % STAGES, t + STAGES - 1);

        unsigned bse = sb + (unsigned)(t % STAGES) * STB;
        unsigned tA = bse, tB = bse + TILB;

        #pragma unroll
        for (int ks = 0; ks < 4; ks++) {
            int kc = ks * 2 + qh;
            unsigned bh[4][2];
            #pragma unroll
            for (int p = 0; p < 2; p++) {
                unsigned off = (unsigned)(boff[p] + ((kc ^ bsw[p]) << 4));
                unsigned q0, q1, q2, q3;
                ldsm4(q0, q1, q2, q3, tB + off);
                bh[2 * p][0] = q0; bh[2 * p + 1][0] = q1;
                bh[2 * p][1] = q2; bh[2 * p + 1][1] = q3;
            }
            #pragma unroll
            for (int mt = 0; mt < 4; mt++) {
                unsigned off = (unsigned)(aoff[mt] + ((kc ^ asw[mt]) << 4));
                unsigned ah[4];
                ldsm4(ah[0], ah[1], ah[2], ah[3], tA + off);
                #pragma unroll
                for (int nt = 0; nt < 4; nt++)
                    mma16(acc[mt][nt], ah, bh[nt]);
            }
        }
    }
}

// stage acc tile into smem [128][132]
__device__ __forceinline__ void stage_acc(float acc[4][4][4], float* stage) {
    int lane = threadIdx.x & 31, wid = threadIdx.x >> 5;
    int wm = wid & 1, wn = wid >> 1;
    #pragma unroll
    for (int mt = 0; mt < 4; mt++) {
        #pragma unroll
        for (int nt = 0; nt < 4; nt++) {
            #pragma unroll
            for (int h = 0; h < 2; h++) {
                int ml = wm * 64 + mt * 16 + (lane >> 2) + h * 8;
                #pragma unroll
                for (int j = 0; j < 2; j++) {
                    int nl = wn * 32 + nt * 8 + (lane & 3) * 2 + j;
                    stage[ml * 132 + nl] = acc[mt][nt][h * 2 + j];
                }
            }
        }
    }
}

// ---------------- K_prep ------------------------------------------------------
__global__ void __launch_bounds__(256) k_prep(const float* __restrict__ x,
                                              const float* __restrict__ th_w,
                                              const float* __restrict__ ph_w,
                                              const float* __restrict__ g_w,
                                              const float* __restrict__ W_w) {
    __shared__ float s[64][50];
    int bx = blockIdx.x;
    if (bx < 8192) {
        int b = bx >> 5, c0 = (bx & 31) * 64;
        const float* xb = x + (size_t)b * CN;
        for (int e = threadIdx.x; e < 64 * NN; e += 256) {
            int cl = e / NN, n = e - cl * NN;
            s[cl][n] = xb[(c0 + cl) * NN + n];
        }
        __syncthreads();
        for (int e = threadIdx.x; e < 16 * NN; e += 256) {
            int n = e >> 4, clg = (e & 15) * 4;
            __half h[4], l[4];
            #pragma unroll
            for (int k = 0; k < 4; k++) splith(s[clg + k][n], h[k], l[k]);
            size_t o = ((size_t)b * NN + n) * CC + c0 + clg;
            *reinterpret_cast<uint2*>(d_xh + o) =
                make_uint2(pack2(h[0], h[1]), pack2(h[2], h[3]));
            *reinterpret_cast<uint2*>(d_xl + o) =
                make_uint2(pack2(l[0], l[1]), pack2(l[2], l[3]));
        }
    } else {
        int role = (bx - 8192) >> 9;
        size_t base = (size_t)((bx - 8192) & 511) * 4096 + threadIdx.x * 4;
        const float* src = (role == 0) ? th_w : (role == 1) ? ph_w
                         : (role == 2) ? g_w : W_w;
        float4 v[4];
        #pragma unroll
        for (int i = 0; i < 4; i++)
            v[i] = *reinterpret_cast<const float4*>(src + base + i * 1024);
        #pragma unroll
        for (int i = 0; i < 4; i++) {
            size_t idx = base + i * 1024;
            if (role < 2) {
                __half h[4], l[4];
                splith(v[i].x, h[0], l[0]); splith(v[i].y, h[1], l[1]);
                splith(v[i].z, h[2], l[2]); splith(v[i].w, h[3], l[3]);
                size_t off = (size_t)role * WSZ + idx;
                *reinterpret_cast<uint2*>(d_wh + off) =
                    make_uint2(pack2(h[0], h[1]), pack2(h[2], h[3]));
                *reinterpret_cast<uint2*>(d_wl + off) =
                    make_uint2(pack2(l[0], l[1]), pack2(l[2], l[3]));
            } else {
                uint2 pk = make_uint2(
                    pack2(__float2half_rn(v[i].x), __float2half_rn(v[i].y)),
                    pack2(__float2half_rn(v[i].z), __float2half_rn(v[i].w)));
                if (role == 2)
                    *reinterpret_cast<uint2*>(d_wh + 2 * (size_t)WSZ + idx) = pk;
                else
                    *reinterpret_cast<uint2*>(d_mwh + idx) = pk;
            }
        }
    }
}

// ---------------- K_mega: spart first || theta/phi (k32x3) || g (k32x4) -------
__global__ void __launch_bounds__(256, 2) k_mega(const float* __restrict__ x,
                                                 const float* __restrict__ fcw,
                                                 const float* __restrict__ th_b,
                                                 const float* __restrict__ ph_b,
                                                 const float* __restrict__ g_b) {
    extern __shared__ __align__(16) __half sdyn[];
    unsigned sb = (unsigned)__cvta_generic_to_shared(sdyn);
    int bid = blockIdx.x;
    int tid = threadIdx.x;

    if (bid >= 256) {
        int gb = bid - 256;
        int role = gb / 784;           // 0 theta, 1 phi, 2 g
        int lb = gb - role * 784;
        int n0 = (lb & 7) * 128, m0 = (lb >> 3) * 128;
        float acc[4][4][4] = {};
        const float* bias;
        if (role < 2) {
            const ptrdiff_t DXL = d_xl - d_xh;
            const ptrdiff_t DWL = d_wl - d_wh;
            const __half* wh = d_wh + (size_t)role * WSZ + (size_t)n0 * CC;
            gemm_core<3, 3, CC>(d_xh + (size_t)m0 * CC, DXL, wh, DWL, sb, acc);
            bias = (role == 0) ? th_b : ph_b;
        } else {
            const __half* wh = d_wh + 2 * (size_t)WSZ + (size_t)n0 * CC;
            gemm_core<1, 4, CC>(d_xh + (size_t)m0 * CC, 0, wh, 0, sb, acc);
            bias = g_b;
        }
        float* out = d_proj + (size_t)role * BN * II;
        float* stage = (float*)sdyn;
        __syncthreads();
        stage_acc(acc, stage);
        __syncthreads();
        for (int e = tid; e < 128 * 128; e += 256) {
            int ml = e >> 7, ql = e & 127;
            out[(size_t)(m0 + ml) * II + n0 + ql] = stage[ml * 132 + ql] + bias[n0 + ql];
        }
    } else {
        int sid = bid;
        int b0 = (sid & 7) * 32;
        int ks = sid >> 3;
        float* fc_s = (float*)sdyn;
        float* x_s  = fc_s + 49 * 65;
        int bg = tid >> 5, jg = tid & 31;
        float acc[4][2] = {};
        for (int kc = 0; kc < KPER / 64; kc++) {
            int kb = ks * KPER + kc * 64;
            for (int e = tid; e < 49 * 64; e += 256) {
                int j = e >> 6, kk = e & 63;
                fc_s[j * 65 + kk] = fcw[(size_t)j * CN + kb + kk];
            }
            for (int e = tid; e < 32 * 64; e += 256) {
                int bl = e >> 6, kk = e & 63;
                x_s[bl * 65 + kk] = x[(size_t)(b0 + bl) * CN + kb + kk];
            }
            __syncthreads();
            #pragma unroll 4
            for (int kk = 0; kk < 64; kk++) {
                float f0 = fc_s[jg * 65 + kk];
                float f1 = (jg < 17) ? fc_s[(jg + 32) * 65 + kk] : 0.f;
                #pragma unroll
                for (int i = 0; i < 4; i++) {
                    float xv = x_s[(bg * 4 + i) * 65 + kk];
                    acc[i][0] += xv * f0; acc[i][1] += xv * f1;
                }
            }
            __syncthreads();
        }
        #pragma unroll
        for (int i = 0; i < 4; i++) {
            int b = b0 + bg * 4 + i;
            d_spart[((size_t)ks * BB + b) * NN + jg] = acc[i][0];
            if (jg + 32 < NN)
                d_spart[((size_t)ks * BB + b) * NN + jg + 32] = acc[i][1];
        }
    }
}

// ---------------- K_post: attention || sred (R14 order) -------------------------
__global__ void __launch_bounds__(256) k_post(const float* __restrict__ fcb) {
    __shared__ float th_s[4][49][17];
    __shared__ float ph_s[4][49][17];
    __shared__ float sc[49][52];

    if (blockIdx.x >= BB) {   // --- sred ---
        int b = blockIdx.x - BB, j = threadIdx.x;
        if (j < NN) {
            float s = fcb[j];
            for (int ks = 0; ks < KSPL; ks++)
                s += d_spart[((size_t)ks * BB + b) * NN + j];
            d_sp[b * NN + j] = s;
        }
        return;
    }

    const float* tx = d_proj;
    const float* px = d_proj + (size_t)BN * II;
    const float* gx = d_proj + (size_t)2 * BN * II;

    int b = blockIdx.x;
    int tid = threadIdx.x;
    int g = tid >> 6, t = tid & 63;
    int ng = t >> 3, mg = t & 7;
    bool act = (ng < 7) && (mg < 7);

    float acc[7][7] = {};
    for (int kt = 0; kt < 16; kt++) {
        int kb = g * 256 + kt * 16;
        for (int e = t; e < 49 * 16; e += 64) {
            int r = e >> 4, kk = e & 15;
            th_s[g][r][kk] = tx[((size_t)b * NN + r) * II + kb + kk];
            ph_s[g][r][kk] = px[((size_t)b * NN + r) * II + kb + kk];
        }
        __syncthreads();
        if (act) {
            #pragma unroll
            for (int kk = 0; kk < 16; kk++) {
                float av[7], bv[7];
                #pragma unroll
                for (int i = 0; i < 7; i++) av[i] = th_s[g][ng * 7 + i][kk];
                #pragma unroll
                for (int j = 0; j < 7; j++) bv[j] = ph_s[g][mg * 7 + j][kk];
                #pragma unroll
                for (int i = 0; i < 7; i++)
                    #pragma unroll
                    for (int j = 0; j < 7; j++)
                        acc[i][j] += av[i] * bv[j];
            }
        }
        __syncthreads();
    }
    for (int gg = 0; gg < 4; gg++) {
        if (g == gg && act) {
            #pragma unroll
            for (int i = 0; i < 7; i++)
                #pragma unroll
                for (int j = 0; j < 7; j++) {
                    if (gg == 0) sc[ng * 7 + i][mg * 7 + j] = acc[i][j];
                    else         sc[ng * 7 + i][mg * 7 + j] += acc[i][j];
                }
        }
        __syncthreads();
    }
    if (tid < 49) {
        float mx = -1e30f;
        for (int m = 0; m < NN; m++) mx = fmaxf(mx, sc[tid][m]);
        float s = 0.f;
        for (int m = 0; m < NN; m++) {
            float e = expf(sc[tid][m] - mx);
            sc[tid][m] = e; s += e;
        }
        float inv = 1.f / s;
        for (int m = 0; m < NN; m++) sc[tid][m] *= inv;
    }
    __syncthreads();
    for (int op = 0; op < 4; op++) {
        int o = op * 256 + tid;
        float a2[49];
        #pragma unroll
        for (int n = 0; n < NN; n++) a2[n] = 0.f;
        for (int m = 0; m < NN; m++) {
            float gv = gx[((size_t)b * NN + m) * II + o];
            #pragma unroll
            for (int n = 0; n < NN; n++) a2[n] += sc[n][m] * gv;
        }
        for (int n = 0; n < NN; n++)
            d_maph[((size_t)b * NN + n) * II + o] = __float2half_rn(a2[n]);
    }
}

// ---------------- K_mask: mask GEMM (k64 core) + staged epilogue ---------------
__global__ void __launch_bounds__(256, 2) k_mask_mma(const float* __restrict__ x,
                                                     float* __restrict__ out) {
    extern __shared__ __align__(16) __half sdyn[];
    unsigned sb = (unsigned)__cvta_generic_to_shared(sdyn);
    int n0 = blockIdx.x * 128;
    int m0 = blockIdx.y * 128;
    int tid = threadIdx.x;
    float acc[4][4][4] = {};
    gemm_core64<II>(d_mwh + (size_t)m0 * II, d_maph + (size_t)n0 * II, sb, acc);

    float* stage = (float*)sdyn;
    __syncthreads();
    stage_acc(acc, stage);
    __syncthreads();
    for (int e = tid; e < 128 * 128; e += 256) {
        int cl = e >> 7, ql = e & 127;
        int q = n0 + ql;
        int b = q / 49, n = q - b * 49;
        size_t idx = ((size_t)b * CC + m0 + cl) * NN + n;
        out[idx] = x[idx] + d_sp[q] * stage[cl * 132 + ql];
    }
}

// ---------------------------------------------------------------------------
extern "C" void kernel_launch(void* const* d_in, const int* in_sizes, int n_in,
                              void* d_out, int out_size) {
    const float* x    = (const float*)d_in[0];
    const float* g_w  = (const float*)d_in[1];
    const float* g_b  = (const float*)d_in[2];
    const float* th_w = (const float*)d_in[3];
    const float* th_b = (const float*)d_in[4];
    const float* ph_w = (const float*)d_in[5];
    const float* ph_b = (const float*)d_in[6];
    const float* W_w  = (const float*)d_in[7];
    const float* fc_w = (const float*)d_in[8];
    const float* fc_b = (const float*)d_in[9];
    float* out = (float*)d_out;
    (void)in_sizes; (void)n_in; (void)out_size;

    const int SMEGA = 96 * 1024;   // k32x3 NSPLIT3 / k32x4 NSPLIT1 / stage 67.6KB
    const int SMASK = 96 * 1024;   // k64x3 pipeline; stage epilogue fits
    cudaFuncSetAttribute(k_mega,     cudaFuncAttributeMaxDynamicSharedMemorySize, SMEGA);
    cudaFuncSetAttribute(k_mask_mma, cudaFuncAttributeMaxDynamicSharedMemorySize, SMASK);

    k_prep<<<8192 + 4 * 512, 256>>>(x, th_w, ph_w, g_w, W_w);
    k_mega<<<2608, 256, SMEGA>>>(x, fc_w, th_b, ph_b, g_b);
    k_post<<<2 * BB, 256>>>(fc_b);
    k_mask_mma<<<dim3(BN / 128, CC / 128), 256, SMASK>>>(x, out);
}